// round 4
// baseline (speedup 1.0000x reference)
#include <cuda_runtime.h>
#include <cuda_bf16.h>
#include <cstdint>

#define BATCH 1024

// ---------------- scratch (static device globals; no allocation) ----------------
__device__ float g_h1[BATCH * 32 * 20 * 20];   // conv1 out
__device__ float g_h2[BATCH * 64 * 9 * 9];     // conv2 out
__device__ float g_h3[BATCH * 3136];           // conv3 out flattened

// bf16 hi/lo split operands for tensor-core GEMMs
__device__ __nv_bfloat16 g_Ah[BATCH * 3136];   // h3 split
__device__ __nv_bfloat16 g_Al[BATCH * 3136];
__device__ __nv_bfloat16 g_Wh[512 * 3136];     // lin1_w split
__device__ __nv_bfloat16 g_Wl[512 * 3136];
__device__ __nv_bfloat16 g_A2h[BATCH * 512];   // h4 split (fc1 output)
__device__ __nv_bfloat16 g_A2l[BATCH * 512];
#define NPAD 3648                               // 57 * 64
__device__ __nv_bfloat16 g_W2h[NPAD * 512];    // heads_w repacked [n=k*18+a][d], zero pad
__device__ __nv_bfloat16 g_W2l[NPAD * 512];

// ============================ helpers ============================
__device__ __forceinline__ uint32_t smem_u32(const void* p) {
    uint32_t a;
    asm("{ .reg .u64 t; cvta.to.shared.u64 t, %1; cvt.u32.u64 %0, t; }"
        : "=r"(a) : "l"(p));
    return a;
}

__device__ __forceinline__ void ldsm4(uint32_t* r, uint32_t addr) {
    asm volatile("ldmatrix.sync.aligned.m8n8.x4.shared.b16 {%0,%1,%2,%3}, [%4];"
                 : "=r"(r[0]), "=r"(r[1]), "=r"(r[2]), "=r"(r[3]) : "r"(addr));
}

__device__ __forceinline__ void mma_bf16(float* d, const uint32_t* a,
                                         uint32_t b0, uint32_t b1) {
    asm volatile(
        "mma.sync.aligned.m16n8k16.row.col.f32.bf16.bf16.f32 "
        "{%0,%1,%2,%3}, {%4,%5,%6,%7}, {%8,%9}, {%0,%1,%2,%3};"
        : "+f"(d[0]), "+f"(d[1]), "+f"(d[2]), "+f"(d[3])
        : "r"(a[0]), "r"(a[1]), "r"(a[2]), "r"(a[3]), "r"(b0), "r"(b1));
}

__device__ __forceinline__ void split_bf16(float v, __nv_bfloat16& h, __nv_bfloat16& l) {
    h = __float2bfloat16(v);
    l = __float2bfloat16(v - __bfloat162float(h));
}

// =====================================================================
// conv1: x[b][4][84][84] -> h1[b][32][20][20], k=8, stride=4, + bias, relu
// =====================================================================
__global__ __launch_bounds__(512) void conv1_kernel(
    const float* __restrict__ x, const float* __restrict__ w,
    const float* __restrict__ bias)
{
    extern __shared__ float sm[];
    float* in_s = sm;            // 28224 floats
    float* w_s  = sm + 28224;    // 8192 floats

    const int b   = blockIdx.x;
    const int tid = threadIdx.x;

    const float* xg = x + b * 28224;
    for (int idx = tid; idx < 28224; idx += blockDim.x) {
        int ic  = idx / 7056;
        int rem = idx - ic * 7056;
        int y   = rem / 84;
        int xx  = rem - y * 84;
        in_s[((ic * 84 + y) * 4 + (xx & 3)) * 21 + (xx >> 2)] = xg[idx];
    }
    for (int idx = tid; idx < 8192; idx += blockDim.x) {
        int oc = idx >> 8;
        int k  = idx & 255;
        w_s[k * 32 + oc] = w[idx];
    }
    __syncthreads();

    if (tid < 400) {
        const int ocg = tid / 100;
        const int sp  = tid - ocg * 100;
        const int ox  = sp % 20;
        const int oyB = (sp / 20) * 4;

        float acc[8][4];
        #pragma unroll
        for (int j = 0; j < 8; j++)
            #pragma unroll
            for (int i = 0; i < 4; i++) acc[j][i] = 0.f;

        for (int ic = 0; ic < 4; ic++) {
            for (int ky = 0; ky < 8; ky++) {
                int rb[4];
                #pragma unroll
                for (int i = 0; i < 4; i++)
                    rb[i] = ((ic * 84 + (oyB + i) * 4 + ky) * 4) * 21 + ox;
                const int kbase = (ic * 8 + ky) * 8;
                #pragma unroll
                for (int kx = 0; kx < 8; kx++) {
                    float iv[4];
                    #pragma unroll
                    for (int i = 0; i < 4; i++)
                        iv[i] = in_s[rb[i] + (kx & 3) * 21 + (kx >> 2)];
                    const float4* wp = reinterpret_cast<const float4*>(
                        w_s + (kbase + kx) * 32 + ocg * 8);
                    float4 wa = wp[0], wb = wp[1];
                    #pragma unroll
                    for (int i = 0; i < 4; i++) {
                        acc[0][i] += wa.x * iv[i];
                        acc[1][i] += wa.y * iv[i];
                        acc[2][i] += wa.z * iv[i];
                        acc[3][i] += wa.w * iv[i];
                        acc[4][i] += wb.x * iv[i];
                        acc[5][i] += wb.y * iv[i];
                        acc[6][i] += wb.z * iv[i];
                        acc[7][i] += wb.w * iv[i];
                    }
                }
            }
        }
        float* ob = g_h1 + b * 12800;
        #pragma unroll
        for (int j = 0; j < 8; j++) {
            float bb = bias[ocg * 8 + j];
            #pragma unroll
            for (int i = 0; i < 4; i++) {
                float v = acc[j][i] + bb;
                ob[(ocg * 8 + j) * 400 + (oyB + i) * 20 + ox] = fmaxf(v, 0.f);
            }
        }
    }
}

// =====================================================================
// conv2: h1 -> h2[b][64][9][9], k=4, stride=2, + bias, relu
// =====================================================================
__global__ __launch_bounds__(256) void conv2_kernel(
    const float* __restrict__ w, const float* __restrict__ bias)
{
    extern __shared__ float sm[];
    float* in_s = sm;            // 12800
    float* w_s  = sm + 12800;    // 32768

    const int b   = blockIdx.x;
    const int tid = threadIdx.x;

    const float* xg = g_h1 + b * 12800;
    for (int idx = tid; idx < 12800; idx += blockDim.x) {
        int c   = idx / 400;
        int rem = idx - c * 400;
        int y   = rem / 20;
        int xx  = rem - y * 20;
        in_s[((c * 20 + y) * 2 + (xx & 1)) * 10 + (xx >> 1)] = xg[idx];
    }
    for (int idx = tid; idx < 32768; idx += blockDim.x) {
        int oc = idx >> 9;
        int k  = idx & 511;
        w_s[k * 64 + oc] = w[idx];
    }
    __syncthreads();

    if (tid < 216) {
        const int ocg = tid / 27;
        const int r   = tid - ocg * 27;
        const int oyg = r / 9;
        const int ox  = r - oyg * 9;

        float acc[8][3];
        #pragma unroll
        for (int j = 0; j < 8; j++)
            #pragma unroll
            for (int i = 0; i < 3; i++) acc[j][i] = 0.f;

        for (int c = 0; c < 32; c++) {
            #pragma unroll
            for (int ky = 0; ky < 4; ky++) {
                #pragma unroll
                for (int kx = 0; kx < 4; kx++) {
                    const int p  = kx & 1;
                    const int xq = ox + (kx >> 1);
                    float iv[3];
                    #pragma unroll
                    for (int i = 0; i < 3; i++) {
                        int y = (oyg * 3 + i) * 2 + ky;
                        iv[i] = in_s[((c * 20 + y) * 2 + p) * 10 + xq];
                    }
                    const int k = (c * 4 + ky) * 4 + kx;
                    const float4* wp = reinterpret_cast<const float4*>(
                        w_s + k * 64 + ocg * 8);
                    float4 wa = wp[0], wb = wp[1];
                    #pragma unroll
                    for (int i = 0; i < 3; i++) {
                        acc[0][i] += wa.x * iv[i];
                        acc[1][i] += wa.y * iv[i];
                        acc[2][i] += wa.z * iv[i];
                        acc[3][i] += wa.w * iv[i];
                        acc[4][i] += wb.x * iv[i];
                        acc[5][i] += wb.y * iv[i];
                        acc[6][i] += wb.z * iv[i];
                        acc[7][i] += wb.w * iv[i];
                    }
                }
            }
        }
        float* ob = g_h2 + b * 5184;
        #pragma unroll
        for (int j = 0; j < 8; j++) {
            float bb = bias[ocg * 8 + j];
            #pragma unroll
            for (int i = 0; i < 3; i++) {
                float v = acc[j][i] + bb;
                ob[(ocg * 8 + j) * 81 + (oyg * 3 + i) * 9 + ox] = fmaxf(v, 0.f);
            }
        }
    }
}

// =====================================================================
// conv3: h2 -> h3[b][3136], k=3, stride=1, + bias, relu
// =====================================================================
__global__ __launch_bounds__(256) void conv3_kernel(
    const float* __restrict__ w, const float* __restrict__ bias)
{
    extern __shared__ float sm[];
    float* in_s = sm;            // 2*5200
    float* w_s  = sm + 10400;    // 36864

    const int b2  = blockIdx.x * 2;
    const int tid = threadIdx.x;

    for (int idx = tid; idx < 10368; idx += blockDim.x) {
        int img = idx / 5184;
        int rem = idx - img * 5184;
        in_s[img * 5200 + rem] = g_h2[(b2 + img) * 5184 + rem];
    }
    for (int idx = tid; idx < 36864; idx += blockDim.x) {
        int oc = idx / 576;
        int k  = idx - oc * 576;
        w_s[k * 64 + oc] = w[idx];
    }
    __syncthreads();

    if (tid < 224) {
        const int img = tid / 112;
        const int r   = tid - img * 112;
        const int ocg = r / 7;
        const int ox  = r - ocg * 7;
        const float* ib = in_s + img * 5200;

        float acc[4][7];
        #pragma unroll
        for (int j = 0; j < 4; j++)
            #pragma unroll
            for (int i = 0; i < 7; i++) acc[j][i] = 0.f;

        for (int c = 0; c < 64; c++) {
            const float* ic_base = ib + c * 81;
            #pragma unroll
            for (int ky = 0; ky < 3; ky++) {
                #pragma unroll
                for (int kx = 0; kx < 3; kx++) {
                    float iv[7];
                    #pragma unroll
                    for (int i = 0; i < 7; i++)
                        iv[i] = ic_base[(i + ky) * 9 + ox + kx];
                    const int k = c * 9 + ky * 3 + kx;
                    const float4* wp = reinterpret_cast<const float4*>(
                        w_s + k * 64 + ocg * 4);
                    float4 wa = wp[0];
                    #pragma unroll
                    for (int i = 0; i < 7; i++) {
                        acc[0][i] += wa.x * iv[i];
                        acc[1][i] += wa.y * iv[i];
                        acc[2][i] += wa.z * iv[i];
                        acc[3][i] += wa.w * iv[i];
                    }
                }
            }
        }
        float* ob = g_h3 + (b2 + img) * 3136;
        #pragma unroll
        for (int j = 0; j < 4; j++) {
            float bb = bias[ocg * 4 + j];
            #pragma unroll
            for (int i = 0; i < 7; i++) {
                float v = acc[j][i] + bb;
                ob[(ocg * 4 + j) * 49 + i * 7 + ox] = fmaxf(v, 0.f);
            }
        }
    }
}

// =====================================================================
// conversion kernels: fp32 -> bf16 hi/lo split
// =====================================================================
__global__ void cvt_h3_kernel() {
    int i = blockIdx.x * blockDim.x + threadIdx.x;
    if (i < BATCH * 3136) {
        __nv_bfloat16 h, l;
        split_bf16(g_h3[i], h, l);
        g_Ah[i] = h; g_Al[i] = l;
    }
}
__global__ void cvt_fc1w_kernel(const float* __restrict__ w) {
    int i = blockIdx.x * blockDim.x + threadIdx.x;
    if (i < 512 * 3136) {
        __nv_bfloat16 h, l;
        split_bf16(w[i], h, l);
        g_Wh[i] = h; g_Wl[i] = l;
    }
}
__global__ void cvt_headsw_kernel(const float* __restrict__ hw) {
    int j = blockIdx.x * blockDim.x + threadIdx.x;
    if (j < NPAD * 512) {
        int n = j >> 9;
        int d = j & 511;
        float v = (n < 3600) ? hw[(n / 18) * 9216 + d * 18 + (n % 18)] : 0.f;
        __nv_bfloat16 h, l;
        split_bf16(v, h, l);
        g_W2h[j] = h; g_W2l[j] = l;
    }
}

// =====================================================================
// GEMM core (mma.sync bf16, hi/lo split). CTA tile 64x64, 256 thr,
// warp tile 32x16 (warps 2M x 4N), K-chunk 32, double-buffered smem.
// smem tile pitch 40 bf16 (80B) -> conflict-free ldmatrix.
// =====================================================================
#define GP 40            // smem row pitch in bf16
#define TILE_E (64 * GP) // bf16 elements per tile per stage

struct Frag { uint32_t r[4]; };

// One K-chunk of compute: reads 4 tiles (Ah,Al,Wh,Wl) from smem stage base.
__device__ __forceinline__ void gemm_chunk(
    uint32_t sbase,          // smem u32 addr of stage (4 tiles consecutive)
    int wm, int wn, int lane, float acc[2][2][4])
{
    const int lrow = lane & 15;
    const int lseg = (lane >> 4) & 1;

    Frag aH[2][2], aL[2][2];       // [mi][ks]
    uint32_t bH[2][2][2], bL[2][2][2];   // [ks][ni][2]

    #pragma unroll
    for (int mi = 0; mi < 2; mi++) {
        #pragma unroll
        for (int ks = 0; ks < 2; ks++) {
            uint32_t off = (uint32_t)((wm * 32 + mi * 16 + lrow) * GP + ks * 16 + lseg * 8) * 2;
            ldsm4(aH[mi][ks].r, sbase + 0 * TILE_E * 2 + off);
            ldsm4(aL[mi][ks].r, sbase + 1 * TILE_E * 2 + off);
        }
    }
    #pragma unroll
    for (int ks = 0; ks < 2; ks++) {
        uint32_t off = (uint32_t)((wn * 16 + lrow) * GP + ks * 16 + lseg * 8) * 2;
        uint32_t t[4];
        ldsm4(t, sbase + 2 * TILE_E * 2 + off);
        bH[ks][0][0] = t[0]; bH[ks][0][1] = t[2];
        bH[ks][1][0] = t[1]; bH[ks][1][1] = t[3];
        ldsm4(t, sbase + 3 * TILE_E * 2 + off);
        bL[ks][0][0] = t[0]; bL[ks][0][1] = t[2];
        bL[ks][1][0] = t[1]; bL[ks][1][1] = t[3];
    }
    #pragma unroll
    for (int ks = 0; ks < 2; ks++)
        #pragma unroll
        for (int mi = 0; mi < 2; mi++)
            #pragma unroll
            for (int ni = 0; ni < 2; ni++) {
                mma_bf16(acc[mi][ni], aH[mi][ks].r, bH[ks][ni][0], bH[ks][ni][1]);
                mma_bf16(acc[mi][ni], aH[mi][ks].r, bL[ks][ni][0], bL[ks][ni][1]);
                mma_bf16(acc[mi][ni], aL[mi][ks].r, bH[ks][ni][0], bH[ks][ni][1]);
            }
}

// Store one thread's 16B chunk into padded smem tile.
__device__ __forceinline__ void store_tile(__nv_bfloat16* s, int row, int q, uint4 v) {
    *reinterpret_cast<uint4*>(s + row * GP + q * 8) = v;
}

// =====================================================================
// fc1: C[1024x512] = Ah/l[1024x3136] x Wh/l[512x3136]^T, +bias, relu,
// write bf16 split to g_A2h/g_A2l.
// =====================================================================
__global__ __launch_bounds__(256) void fc1_mma_kernel(const float* __restrict__ bias)
{
    __shared__ __nv_bfloat16 sm[2][4][TILE_E];
    const int tid = threadIdx.x;
    const int wid = tid >> 5, lane = tid & 31;
    const int wm = wid >> 2, wn = wid & 3;
    const int m0 = blockIdx.y * 64;
    const int n0 = blockIdx.x * 64;

    const int row = tid >> 2;     // 0..63
    const int q   = tid & 3;      // 0..3 (8 bf16 each)

    float acc[2][2][4];
    #pragma unroll
    for (int a = 0; a < 2; a++)
        #pragma unroll
        for (int b = 0; b < 2; b++)
            #pragma unroll
            for (int c = 0; c < 4; c++) acc[a][b][c] = 0.f;

    const __nv_bfloat16* pAh = g_Ah + (size_t)(m0 + row) * 3136 + q * 8;
    const __nv_bfloat16* pAl = g_Al + (size_t)(m0 + row) * 3136 + q * 8;
    const __nv_bfloat16* pWh = g_Wh + (size_t)(n0 + row) * 3136 + q * 8;
    const __nv_bfloat16* pWl = g_Wl + (size_t)(n0 + row) * 3136 + q * 8;

    uint4 rAh = *reinterpret_cast<const uint4*>(pAh);
    uint4 rAl = *reinterpret_cast<const uint4*>(pAl);
    uint4 rWh = *reinterpret_cast<const uint4*>(pWh);
    uint4 rWl = *reinterpret_cast<const uint4*>(pWl);

    const uint32_t sb = smem_u32(&sm[0][0][0]);
    int s = 0;
    const int NIT = 3136 / 32;   // 98

    for (int it = 0; it < NIT; it++) {
        store_tile(sm[s][0], row, q, rAh);
        store_tile(sm[s][1], row, q, rAl);
        store_tile(sm[s][2], row, q, rWh);
        store_tile(sm[s][3], row, q, rWl);
        __syncthreads();
        if (it + 1 < NIT) {
            int k0 = (it + 1) * 32;
            rAh = *reinterpret_cast<const uint4*>(pAh + k0);
            rAl = *reinterpret_cast<const uint4*>(pAl + k0);
            rWh = *reinterpret_cast<const uint4*>(pWh + k0);
            rWl = *reinterpret_cast<const uint4*>(pWl + k0);
        }
        gemm_chunk(sb + (uint32_t)s * 4 * TILE_E * 2, wm, wn, lane, acc);
        s ^= 1;
    }

    // epilogue
    const int group = lane >> 2, tig = lane & 3;
    #pragma unroll
    for (int mi = 0; mi < 2; mi++) {
        #pragma unroll
        for (int ni = 0; ni < 2; ni++) {
            int colg = n0 + wn * 16 + ni * 8 + 2 * tig;
            float b0 = bias[colg], b1 = bias[colg + 1];
            #pragma unroll
            for (int half = 0; half < 2; half++) {
                int rowg = m0 + wm * 32 + mi * 16 + group + half * 8;
                float v0 = fmaxf(acc[mi][ni][half * 2]     + b0, 0.f);
                float v1 = fmaxf(acc[mi][ni][half * 2 + 1] + b1, 0.f);
                __nv_bfloat16 h0, l0, h1, l1;
                split_bf16(v0, h0, l0);
                split_bf16(v1, h1, l1);
                __nv_bfloat162 ph; ph.x = h0; ph.y = h1;
                __nv_bfloat162 pl; pl.x = l0; pl.y = l1;
                *reinterpret_cast<__nv_bfloat162*>(&g_A2h[(size_t)rowg * 512 + colg]) = ph;
                *reinterpret_cast<__nv_bfloat162*>(&g_A2l[(size_t)rowg * 512 + colg]) = pl;
            }
        }
    }
}

// =====================================================================
// heads: C[1024xNPAD] = A2h/l[1024x512] x W2h/l[NPADx512]^T, +hb, scatter
// out[head][b][a], head = n/18, a = n%18, n < 3600.
// =====================================================================
__global__ __launch_bounds__(256) void heads_mma_kernel(
    const float* __restrict__ hb, float* __restrict__ out)
{
    __shared__ __nv_bfloat16 sm[2][4][TILE_E];
    const int tid = threadIdx.x;
    const int wid = tid >> 5, lane = tid & 31;
    const int wm = wid >> 2, wn = wid & 3;
    const int m0 = blockIdx.y * 64;
    const int n0 = blockIdx.x * 64;

    const int row = tid >> 2;
    const int q   = tid & 3;

    float acc[2][2][4];
    #pragma unroll
    for (int a = 0; a < 2; a++)
        #pragma unroll
        for (int b = 0; b < 2; b++)
            #pragma unroll
            for (int c = 0; c < 4; c++) acc[a][b][c] = 0.f;

    const __nv_bfloat16* pAh = g_A2h + (size_t)(m0 + row) * 512 + q * 8;
    const __nv_bfloat16* pAl = g_A2l + (size_t)(m0 + row) * 512 + q * 8;
    const __nv_bfloat16* pWh = g_W2h + (size_t)(n0 + row) * 512 + q * 8;
    const __nv_bfloat16* pWl = g_W2l + (size_t)(n0 + row) * 512 + q * 8;

    uint4 rAh = *reinterpret_cast<const uint4*>(pAh);
    uint4 rAl = *reinterpret_cast<const uint4*>(pAl);
    uint4 rWh = *reinterpret_cast<const uint4*>(pWh);
    uint4 rWl = *reinterpret_cast<const uint4*>(pWl);

    const uint32_t sb = smem_u32(&sm[0][0][0]);
    int s = 0;
    const int NIT = 512 / 32;    // 16

    for (int it = 0; it < NIT; it++) {
        store_tile(sm[s][0], row, q, rAh);
        store_tile(sm[s][1], row, q, rAl);
        store_tile(sm[s][2], row, q, rWh);
        store_tile(sm[s][3], row, q, rWl);
        __syncthreads();
        if (it + 1 < NIT) {
            int k0 = (it + 1) * 32;
            rAh = *reinterpret_cast<const uint4*>(pAh + k0);
            rAl = *reinterpret_cast<const uint4*>(pAl + k0);
            rWh = *reinterpret_cast<const uint4*>(pWh + k0);
            rWl = *reinterpret_cast<const uint4*>(pWl + k0);
        }
        gemm_chunk(sb + (uint32_t)s * 4 * TILE_E * 2, wm, wn, lane, acc);
        s ^= 1;
    }

    // epilogue: scatter to out[head][b][a]
    const int group = lane >> 2, tig = lane & 3;
    #pragma unroll
    for (int mi = 0; mi < 2; mi++) {
        #pragma unroll
        for (int ni = 0; ni < 2; ni++) {
            int colg = n0 + wn * 16 + ni * 8 + 2 * tig;
            #pragma unroll
            for (int half = 0; half < 2; half++) {
                int rowg = m0 + wm * 32 + mi * 16 + group + half * 8;
                #pragma unroll
                for (int e = 0; e < 2; e++) {
                    int n = colg + e;
                    if (n < 3600) {
                        int head = n / 18;
                        int a    = n - head * 18;
                        float v  = acc[mi][ni][half * 2 + e] + hb[n];
                        out[((size_t)head * 1024 + rowg) * 18 + a] = v;
                    }
                }
            }
        }
    }
}

// =====================================================================
extern "C" void kernel_launch(void* const* d_in, const int* in_sizes, int n_in,
                              void* d_out, int out_size)
{
    const float* x   = (const float*)d_in[0];
    const float* c1w = (const float*)d_in[1];
    const float* c1b = (const float*)d_in[2];
    const float* c2w = (const float*)d_in[3];
    const float* c2b = (const float*)d_in[4];
    const float* c3w = (const float*)d_in[5];
    const float* c3b = (const float*)d_in[6];
    const float* l1w = (const float*)d_in[7];
    const float* l1b = (const float*)d_in[8];
    const float* hw  = (const float*)d_in[9];
    const float* hb  = (const float*)d_in[10];
    float* out = (float*)d_out;

    const int smem1 = (28224 + 8192) * 4;
    const int smem2 = (12800 + 32768) * 4;
    const int smem3 = (10400 + 36864) * 4;
    cudaFuncSetAttribute(conv1_kernel, cudaFuncAttributeMaxDynamicSharedMemorySize, smem1);
    cudaFuncSetAttribute(conv2_kernel, cudaFuncAttributeMaxDynamicSharedMemorySize, smem2);
    cudaFuncSetAttribute(conv3_kernel, cudaFuncAttributeMaxDynamicSharedMemorySize, smem3);

    conv1_kernel<<<BATCH, 512, smem1>>>(x, c1w, c1b);
    conv2_kernel<<<BATCH, 256, smem2>>>(c2w, c2b);
    conv3_kernel<<<BATCH / 2, 256, smem3>>>(c3w, c3b);

    cvt_fc1w_kernel<<<(512 * 3136 + 255) / 256, 256>>>(l1w);
    cvt_headsw_kernel<<<(NPAD * 512 + 255) / 256, 256>>>(hw);
    cvt_h3_kernel<<<(BATCH * 3136 + 255) / 256, 256>>>();

    fc1_mma_kernel<<<dim3(8, 16), 256>>>(l1b);
    heads_mma_kernel<<<dim3(NPAD / 64, 16), 256>>>(hb, out);
}